// round 6
// baseline (speedup 1.0000x reference)
#include <cuda_runtime.h>

#define BB 64
#define SS 512
#define HH 768
#define LL 9
#define BS (BB*SS)
#define CH 4
#define CLEN 128
#define FULLM 0xffffffffu

__device__ float g_logits[BS*LL];
__device__ float g_num[BB];
__device__ float g_lnM[BB*CH*LL*LL];   // chunk transfer matrices, log2 domain

__device__ __forceinline__ float ex2f(float x){ float y; asm("ex2.approx.ftz.f32 %0,%1;" : "=f"(y) : "f"(x)); return y; }
__device__ __forceinline__ float lg2f(float x){ float y; asm("lg2.approx.ftz.f32 %0,%1;" : "=f"(y) : "f"(x)); return y; }

// ================= 1. GEMM: 2 rows/lane, 8-way k-split, low regs -> occ ~50% =================
__global__ void __launch_bounds__(256) gemm_kernel(const float* __restrict__ hidden,
                                                   const float* __restrict__ W,
                                                   const float* __restrict__ bvec) {
    __shared__ float w_t[LL*HH];   // [l][k]
    __shared__ float b_s[LL];
    int tid = threadIdx.x;
    for (int i = tid; i < HH*LL; i += 256) {
        int k = i / LL, l = i - k*LL;
        w_t[l*HH + k] = W[i];
    }
    if (tid < LL) b_s[tid] = bvec[tid];
    __syncthreads();

    int warp = tid >> 5, ln = tid & 31;
    int li = ln & 7;        // k-split lane
    int rg = ln >> 3;       // row group (2 rows each)
    int row0 = blockIdx.x * 64 + warp * 8 + rg * 2;
    const float* hp = hidden + (size_t)row0 * HH;

    float acc0[LL], acc1[LL];
    #pragma unroll
    for (int l = 0; l < LL; l++) { acc0[l] = 0.f; acc1[l] = 0.f; }

    #pragma unroll 2
    for (int c = 0; c < HH/32; c++) {
        int kb = c*32 + li*4;
        float4 x0 = *reinterpret_cast<const float4*>(hp + kb);
        float4 x1 = *reinterpret_cast<const float4*>(hp + HH + kb);
        #pragma unroll
        for (int l = 0; l < LL; l++) {
            float4 w4 = *reinterpret_cast<const float4*>(w_t + l*HH + kb);
            acc0[l] += x0.x*w4.x; acc1[l] += x1.x*w4.x;
            acc0[l] += x0.y*w4.y; acc1[l] += x1.y*w4.y;
            acc0[l] += x0.z*w4.z; acc1[l] += x1.z*w4.z;
            acc0[l] += x0.w*w4.w; acc1[l] += x1.w*w4.w;
        }
    }
    #pragma unroll
    for (int l = 0; l < LL; l++) {
        float v0 = acc0[l], v1 = acc1[l];
        v0 += __shfl_xor_sync(FULLM, v0, 4); v1 += __shfl_xor_sync(FULLM, v1, 4);
        v0 += __shfl_xor_sync(FULLM, v0, 2); v1 += __shfl_xor_sync(FULLM, v1, 2);
        v0 += __shfl_xor_sync(FULLM, v0, 1); v1 += __shfl_xor_sync(FULLM, v1, 1);
        acc0[l] = v0; acc1[l] = v1;
    }
    if (li == 0) {
        float* op0 = g_logits + (size_t)row0 * LL;
        float* op1 = op0 + LL;
        #pragma unroll
        for (int l = 0; l < LL; l++) { op0[l] = acc0[l] + b_s[l]; op1[l] = acc1[l] + b_s[l]; }
    }
}

// ================= 2. fused: blocks 0..63 viterbi+num+onehot, 64..127 lognorm chunk matrices =================
__global__ void __launch_bounds__(384) fused_kernel(const int* __restrict__ mask,
                                                    const int* __restrict__ labels,
                                                    const float* __restrict__ st,
                                                    const float* __restrict__ en,
                                                    const float* __restrict__ tr,
                                                    float* __restrict__ out) {
    const float L2E = 1.4426950408889634f;
    int bid = blockIdx.x;
    int tid = threadIdx.x;

    __shared__ float em_s[SS*LL];
    __shared__ unsigned char m_sh[SS];
    __shared__ unsigned char bp[SS][16];
    __shared__ unsigned char seg[8][LL][64];
    __shared__ unsigned char chosen[8];
    __shared__ int best_last_sh;

    int b = (bid < BB) ? bid : (bid - BB);
    // ---- stage emissions + mask ----
    {
        const float4* src = reinterpret_cast<const float4*>(g_logits + (size_t)b * SS * LL);
        float4* dst = reinterpret_cast<float4*>(em_s);
        for (int k = tid; k < SS*LL/4; k += 384) dst[k] = src[k];
        const int* mp = mask + b * SS;
        for (int k = tid; k < SS; k += 384) m_sh[k] = (unsigned char)(mp[k] != 0);
    }
    __syncthreads();

    int w = tid >> 5, j = tid & 31;

    if (bid < BB) {
        bool lane9 = (j < LL);
        if (w == 0) {
            // ---------------- exact Viterbi forward ----------------
            float trow[LL];
            #pragma unroll
            for (int i = 0; i < LL; i++) trow[i] = lane9 ? tr[i*LL + j] : 0.f;
            float vs = lane9 ? (st[j] + em_s[j]) : -1e30f;
            float em_c = lane9 ? em_s[LL + j] : 0.f;
            int   m_c  = m_sh[1];
            for (int t = 1; t < SS; t++) {
                float em_n = 0.f; int m_n = 0;
                if (t + 1 < SS) {
                    em_n = lane9 ? em_s[(t+1)*LL + j] : 0.f;
                    m_n  = m_sh[t+1];
                }
                float v[LL];
                #pragma unroll
                for (int i = 0; i < LL; i++) v[i] = __shfl_sync(FULLM, vs, i) + trow[i];
                float m01 = fmaxf(v[0], v[1]), m23 = fmaxf(v[2], v[3]);
                float m45 = fmaxf(v[4], v[5]), m67 = fmaxf(v[6], v[7]);
                float best = fmaxf(fmaxf(fmaxf(m01, m23), fmaxf(m45, m67)), v[8]);
                float nxt = best + em_c;
                int bi = 8;
                #pragma unroll
                for (int i = 7; i >= 0; i--) bi = (v[i] == best) ? i : bi;  // lowest index wins
                if (lane9) bp[t][j] = (unsigned char)(m_c ? bi : j);        // identity if masked
                vs = m_c ? nxt : vs;
                em_c = em_n; m_c = m_n;
            }
            float fin = lane9 ? (vs + en[j]) : -1e30f;
            float bv = -1e30f; int bl = 0;
            #pragma unroll
            for (int i = 0; i < LL; i++) {
                float f = __shfl_sync(FULLM, fin, i);
                if (f > bv) { bv = f; bl = i; }
            }
            if (j == 0) best_last_sh = bl;
        } else if (w == 1) {
            // ---------------- numerator ----------------
            const int* lp = labels + b * SS;
            float acc = 0.f; int cnt = 0;
            for (int t = j; t < SS; t += 32) {
                int m = m_sh[t]; cnt += m;
                if (t >= 1 && m) {
                    int tg = lp[t];   if (tg == -100) tg = 0;
                    int tp = lp[t-1]; if (tp == -100) tp = 0;
                    acc += em_s[t*LL + tg] + tr[tp*LL + tg];
                }
            }
            #pragma unroll
            for (int o = 16; o > 0; o >>= 1) {
                acc += __shfl_down_sync(FULLM, acc, o);
                cnt += __shfl_down_sync(FULLM, cnt, o);
            }
            if (j == 0) {
                int t0 = lp[0]; if (t0 == -100) t0 = 0;
                int lt = lp[cnt - 1]; if (lt == -100) lt = 0;
                g_num[b] = st[t0] + em_s[t0] + acc + en[lt];
            }
        }
        __syncthreads();

        // ---------------- chunk-parallel backtrack: 72 chases ----------------
        if (tid < 72) {
            int c = tid / 9, e = tid - c*9;
            int thi = (c == 7) ? (SS-1) : (c*64 + 64);
            int cur = e;
            for (int t = thi; t >= c*64 + 1; t--) {
                cur = bp[t][cur];
                seg[c][e][t - 1 - c*64] = (unsigned char)cur;
            }
        }
        __syncthreads();
        if (tid == 0) {
            int cur = best_last_sh;
            chosen[7] = (unsigned char)cur;
            for (int c = 7; c >= 1; c--) {
                cur = seg[c][cur][0];
                chosen[c-1] = (unsigned char)cur;
            }
        }
        __syncthreads();

        // ---------------- one-hot write ----------------
        float* outp = out + 1 + (size_t)b * SS * LL;
        int bl = best_last_sh;
        for (int idx = tid; idx < SS*LL; idx += 384) {
            int t = idx / LL;
            int l = idx - t*LL;
            int c = t >> 6;
            int tag = (t == SS-1) ? bl : (int)seg[c][chosen[c]][t & 63];
            outp[idx] = (m_sh[t] && tag == l) ? 1.f : 0.f;
        }
    } else {
        // ---------------- lognorm chunk transfer matrices ----------------
        // warp w: chunk c = w/3, basis trio = w%3; lanes in 3 groups of 9.
        int c = w / 3, trio = w - c*3;
        int lane = j;
        int gg = lane / 9;                       // 0..3
        int jj = lane - gg*9;                    // 0..8 valid (lane<27); lane>=27 harmless
        if (gg > 2) { gg = 0; jj = lane - 27; }
        int gbase = gg * 9;
        bool act = (lane < 27);
        int i = trio*3 + (lane < 27 ? lane/9 : 0);

        float u[LL];
        #pragma unroll
        for (int k = 0; k < LL; k++) u[k] = ex2f(tr[k*LL + jj] * L2E);

        float wv = (act && jj == i) ? 1.f : 0.f;
        int Ce = 0;
        int t0 = c*CLEN + 1;
        int t1 = (c == CH-1) ? (SS-1) : (c*CLEN + CLEN);
        for (int t = t0; t <= t1; t++) {
            float pe = ex2f(em_s[t*LL + jj] * L2E);
            int m = m_sh[t];
            float wi[LL];
            #pragma unroll
            for (int k = 0; k < LL; k++) wi[k] = __shfl_sync(FULLM, wv, gbase + k) * u[k];
            float p = ((wi[0]+wi[1]) + (wi[2]+wi[3])) + ((wi[4]+wi[5]) + (wi[6]+wi[7])) + wi[8];
            float nw = p * pe;
            wv = m ? nw : wv;
            if (((t - t0) & 15) == 15) {         // exact power-of-2 renorm
                float mx = wv;
                #pragma unroll
                for (int k = 0; k < LL; k++) mx = fmaxf(mx, __shfl_sync(FULLM, wv, gbase + k));
                int e = ((__float_as_int(mx) >> 23) & 0xFF) - 127;
                Ce += e;
                wv *= __int_as_float((127 - e) << 23);
            }
        }
        if (act) {
            float lw = lg2f(wv) + (float)Ce;     // -inf ok for unreachable entries
            g_lnM[(((b*CH) + c)*LL + i)*LL + jj] = lw;
        }
    }
}

// ================= 3. combine chunk matrices -> den; loss =================
__global__ void __launch_bounds__(512) combine_loss_kernel(const float* __restrict__ st,
                                                           const float* __restrict__ en,
                                                           float* __restrict__ out) {
    const float L2E = 1.4426950408889634f;
    __shared__ float nd[BB];
    int tid = threadIdx.x;
    int w = tid >> 5, lane = tid & 31;
    int jj = (lane < LL) ? lane : (LL-1);
    bool l9 = (lane < LL);

    for (int b = w; b < BB; b += 16) {
        float Mv[CH][LL];
        #pragma unroll
        for (int c = 0; c < CH; c++)
            #pragma unroll
            for (int i = 0; i < LL; i++)
                Mv[c][i] = g_lnM[(((b*CH) + c)*LL + i)*LL + jj];

        float v = l9 ? (st[lane] + g_logits[(size_t)b*SS*LL + lane]) * L2E : -1e30f;
        #pragma unroll
        for (int c = 0; c < CH; c++) {
            float s[LL];
            #pragma unroll
            for (int i = 0; i < LL; i++) s[i] = __shfl_sync(FULLM, v, i) + Mv[c][i];
            float mx = s[0];
            #pragma unroll
            for (int i = 1; i < LL; i++) mx = fmaxf(mx, s[i]);
            float p = 0.f;
            #pragma unroll
            for (int i = 0; i < LL; i++) p += ex2f(s[i] - mx);
            v = mx + lg2f(p);
        }
        float fv = l9 ? (v + en[lane] * L2E) : -1e30f;
        float s[LL];
        #pragma unroll
        for (int i = 0; i < LL; i++) s[i] = __shfl_sync(FULLM, fv, i);
        float mx = s[0];
        #pragma unroll
        for (int i = 1; i < LL; i++) mx = fmaxf(mx, s[i]);
        float p = 0.f;
        #pragma unroll
        for (int i = 0; i < LL; i++) p += ex2f(s[i] - mx);
        if (lane == 0) nd[b] = g_num[b] - (mx + lg2f(p)) * (1.0f / L2E);
    }
    __syncthreads();
    if (tid < 32) {
        float v = nd[tid] + nd[tid + 32];
        #pragma unroll
        for (int o = 16; o > 0; o >>= 1) v += __shfl_down_sync(FULLM, v, o);
        if (tid == 0) out[0] = -v / (float)BB;
    }
}

extern "C" void kernel_launch(void* const* d_in, const int* in_sizes, int n_in,
                              void* d_out, int out_size) {
    const float* hidden = (const float*)d_in[0];
    const int*   mask   = (const int*)  d_in[1];
    const int*   labels = (const int*)  d_in[2];
    const float* W      = (const float*)d_in[3];
    const float* bvec   = (const float*)d_in[4];
    const float* st     = (const float*)d_in[5];
    const float* en     = (const float*)d_in[6];
    const float* tr     = (const float*)d_in[7];
    float* out = (float*)d_out;

    gemm_kernel<<<BS/64, 256>>>(hidden, W, bvec);
    fused_kernel<<<BB*2, 384>>>(mask, labels, st, en, tr, out);
    combine_loss_kernel<<<1, 512>>>(st, en, out);
}

// round 7
// speedup vs baseline: 1.2057x; 1.2057x over previous
#include <cuda_runtime.h>

#define BB 64
#define SS 512
#define HH 768
#define LL 9
#define BS (BB*SS)
#define CH 4
#define CLEN 128
#define FULLM 0xffffffffu

__device__ float g_logits[BS*LL];
__device__ float g_num[BB];
__device__ float g_lnM[BB*CH*LL*LL];

__device__ __forceinline__ float ex2f(float x){ float y; asm("ex2.approx.ftz.f32 %0,%1;" : "=f"(y) : "f"(x)); return y; }
__device__ __forceinline__ float lg2f(float x){ float y; asm("lg2.approx.ftz.f32 %0,%1;" : "=f"(y) : "f"(x)); return y; }

// ================= 1. GEMM =================
__global__ void __launch_bounds__(256) gemm_kernel(const float* __restrict__ hidden,
                                                   const float* __restrict__ W,
                                                   const float* __restrict__ bvec) {
    __shared__ float w_t[LL*HH];   // [l][k]
    __shared__ float b_s[LL];
    int tid = threadIdx.x;
    for (int i = tid; i < HH*LL; i += 256) {
        int k = i / LL, l = i - k*LL;
        w_t[l*HH + k] = W[i];
    }
    if (tid < LL) b_s[tid] = bvec[tid];
    __syncthreads();

    int warp = tid >> 5, ln = tid & 31;
    int li = ln & 7;        // k-split lane
    int rg = ln >> 3;       // row group (2 rows)
    int row0 = blockIdx.x * 64 + warp * 8 + rg * 2;
    const float* hp = hidden + (size_t)row0 * HH;

    float acc0[LL], acc1[LL];
    #pragma unroll
    for (int l = 0; l < LL; l++) { acc0[l] = 0.f; acc1[l] = 0.f; }

    #pragma unroll 8
    for (int c = 0; c < HH/32; c++) {
        int kb = c*32 + li*4;
        float4 x0 = __ldcs(reinterpret_cast<const float4*>(hp + kb));
        float4 x1 = __ldcs(reinterpret_cast<const float4*>(hp + HH + kb));
        #pragma unroll
        for (int l = 0; l < LL; l++) {
            float4 w4 = *reinterpret_cast<const float4*>(w_t + l*HH + kb);
            acc0[l] += x0.x*w4.x; acc1[l] += x1.x*w4.x;
            acc0[l] += x0.y*w4.y; acc1[l] += x1.y*w4.y;
            acc0[l] += x0.z*w4.z; acc1[l] += x1.z*w4.z;
            acc0[l] += x0.w*w4.w; acc1[l] += x1.w*w4.w;
        }
    }
    #pragma unroll
    for (int l = 0; l < LL; l++) {
        float v0 = acc0[l], v1 = acc1[l];
        v0 += __shfl_xor_sync(FULLM, v0, 4); v1 += __shfl_xor_sync(FULLM, v1, 4);
        v0 += __shfl_xor_sync(FULLM, v0, 2); v1 += __shfl_xor_sync(FULLM, v1, 2);
        v0 += __shfl_xor_sync(FULLM, v0, 1); v1 += __shfl_xor_sync(FULLM, v1, 1);
        acc0[l] = v0; acc1[l] = v1;
    }
    if (li == 0) {
        float* op0 = g_logits + (size_t)row0 * LL;
        float* op1 = op0 + LL;
        #pragma unroll
        for (int l = 0; l < LL; l++) { op0[l] = acc0[l] + b_s[l]; op1[l] = acc1[l] + b_s[l]; }
    }
}

// ================= 2. fused: blocks 0..63 viterbi+num+onehot, 64..127 lognorm chunks =================
// Serial loops are BRANCH-FREE: arrays padded one step (t=512 is a masked no-op).
__global__ void __launch_bounds__(384) fused_kernel(const int* __restrict__ mask,
                                                    const int* __restrict__ labels,
                                                    const float* __restrict__ st,
                                                    const float* __restrict__ en,
                                                    const float* __restrict__ tr,
                                                    float* __restrict__ out) {
    const float L2E = 1.4426950408889634f;
    int bid = blockIdx.x;
    int tid = threadIdx.x;

    __shared__ float em_s[(SS+1)*LL];        // t=512 pad = 0
    __shared__ unsigned char m_sh[SS+1];     // m[512] = 0
    __shared__ unsigned char bp[SS+1][16];
    __shared__ unsigned char seg[8][LL][64];
    __shared__ unsigned char chosen[8];
    __shared__ int best_last_sh;

    int b = (bid < BB) ? bid : (bid - BB);
    // ---- stage emissions + mask + pads ----
    {
        const float4* src = reinterpret_cast<const float4*>(g_logits + (size_t)b * SS * LL);
        float4* dst = reinterpret_cast<float4*>(em_s);
        #pragma unroll
        for (int k = 0; k < 3; k++) dst[tid + k*384] = src[tid + k*384];
        const int* mp = mask + b * SS;
        for (int k = tid; k < SS; k += 384) m_sh[k] = (unsigned char)(mp[k] != 0);
        if (tid < LL) em_s[SS*LL + tid] = 0.f;
        if (tid == 0) m_sh[SS] = 0;
    }
    __syncthreads();

    int w = tid >> 5, j = tid & 31;

    if (bid < BB) {
        bool lane9 = (j < LL);
        if (w == 0) {
            // ---------------- exact Viterbi forward: 512 steps, branch-free ----------------
            float trow[LL];
            #pragma unroll
            for (int i = 0; i < LL; i++) trow[i] = lane9 ? tr[i*LL + j] : 0.f;
            float vs = lane9 ? (st[j] + em_s[j]) : -1e30f;
            for (int tt = 0; tt < 32; tt++) {
                #pragma unroll
                for (int k = 0; k < 16; k++) {
                    int t = tt*16 + k + 1;            // 1..512
                    float em_c = lane9 ? em_s[t*LL + j] : 0.f;
                    int m_c = m_sh[t];
                    float v[LL];
                    #pragma unroll
                    for (int i = 0; i < LL; i++) v[i] = __shfl_sync(FULLM, vs, i) + trow[i];
                    float m01 = fmaxf(v[0], v[1]), m23 = fmaxf(v[2], v[3]);
                    float m45 = fmaxf(v[4], v[5]), m67 = fmaxf(v[6], v[7]);
                    float best = fmaxf(fmaxf(fmaxf(m01, m23), fmaxf(m45, m67)), v[8]);
                    float nxt = best + em_c;
                    int bi = 8;
                    #pragma unroll
                    for (int i = 7; i >= 0; i--) bi = (v[i] == best) ? i : bi;
                    if (lane9) bp[t][j] = (unsigned char)(m_c ? bi : j);
                    vs = m_c ? nxt : vs;
                }
            }
            float fin = lane9 ? (vs + en[j]) : -1e30f;
            float bv = -1e30f; int bl = 0;
            #pragma unroll
            for (int i = 0; i < LL; i++) {
                float f = __shfl_sync(FULLM, fin, i);
                if (f > bv) { bv = f; bl = i; }
            }
            if (j == 0) best_last_sh = bl;
        } else if (w == 1) {
            // ---------------- numerator ----------------
            const int* lp = labels + b * SS;
            float acc = 0.f; int cnt = 0;
            for (int t = j; t < SS; t += 32) {
                int m = m_sh[t]; cnt += m;
                if (t >= 1 && m) {
                    int tg = lp[t];   if (tg == -100) tg = 0;
                    int tp = lp[t-1]; if (tp == -100) tp = 0;
                    acc += em_s[t*LL + tg] + tr[tp*LL + tg];
                }
            }
            #pragma unroll
            for (int o = 16; o > 0; o >>= 1) {
                acc += __shfl_down_sync(FULLM, acc, o);
                cnt += __shfl_down_sync(FULLM, cnt, o);
            }
            if (j == 0) {
                int t0 = lp[0]; if (t0 == -100) t0 = 0;
                int lt = lp[cnt - 1]; if (lt == -100) lt = 0;
                g_num[b] = st[t0] + em_s[t0] + acc + en[lt];
            }
        }
        __syncthreads();

        // ---------------- chunk-parallel backtrack: 72 chases ----------------
        if (tid < 72) {
            int c = tid / 9, e = tid - c*9;
            int thi = (c == 7) ? (SS-1) : (c*64 + 64);
            int cur = e;
            for (int t = thi; t >= c*64 + 1; t--) {
                cur = bp[t][cur];
                seg[c][e][t - 1 - c*64] = (unsigned char)cur;
            }
        }
        __syncthreads();
        if (tid == 0) {
            int cur = best_last_sh;
            chosen[7] = (unsigned char)cur;
            for (int c = 7; c >= 1; c--) {
                cur = seg[c][cur][0];
                chosen[c-1] = (unsigned char)cur;
            }
        }
        __syncthreads();

        // ---------------- one-hot write ----------------
        float* outp = out + 1 + (size_t)b * SS * LL;
        int bl = best_last_sh;
        for (int idx = tid; idx < SS*LL; idx += 384) {
            int t = idx / LL;
            int l = idx - t*LL;
            int c = t >> 6;
            int tag = (t == SS-1) ? bl : (int)seg[c][chosen[c]][t & 63];
            outp[idx] = (m_sh[t] && tag == l) ? 1.f : 0.f;
        }
    } else {
        // ---------------- lognorm chunk transfer matrices (branch-free, 8x16) ----------------
        int c = w / 3, trio = w - c*3;
        int lane = j;
        int gg = lane / 9;
        int jj = lane - gg*9;
        if (gg > 2) { gg = 0; jj = lane - 27; }
        int gbase = gg * 9;
        bool act = (lane < 27);
        int i = trio*3 + (lane < 27 ? lane/9 : 0);

        float u[LL];
        #pragma unroll
        for (int k = 0; k < LL; k++) u[k] = ex2f(tr[k*LL + jj] * L2E);

        float wv = (act && jj == i) ? 1.f : 0.f;
        int Ce = 0;
        int t0 = c*CLEN + 1;
        for (int oo = 0; oo < 8; oo++) {
            #pragma unroll
            for (int k = 0; k < 16; k++) {
                int t = t0 + oo*16 + k;              // covers 128 steps; t=512 masked no-op
                float pe = ex2f(em_s[t*LL + jj] * L2E);
                int m = m_sh[t];
                float wi[LL];
                #pragma unroll
                for (int q = 0; q < LL; q++) wi[q] = __shfl_sync(FULLM, wv, gbase + q) * u[q];
                float p = ((wi[0]+wi[1]) + (wi[2]+wi[3])) + ((wi[4]+wi[5]) + (wi[6]+wi[7])) + wi[8];
                float nw = p * pe;
                wv = m ? nw : wv;
            }
            // exact power-of-2 renorm (once per 16 steps, off the unrolled chain)
            float mx = wv;
            #pragma unroll
            for (int q = 0; q < LL; q++) mx = fmaxf(mx, __shfl_sync(FULLM, wv, gbase + q));
            int e = ((__float_as_int(mx) >> 23) & 0xFF) - 127;
            Ce += e;
            wv *= __int_as_float((127 - e) << 23);
        }
        if (act) {
            float lw = lg2f(wv) + (float)Ce;
            g_lnM[(((b*CH) + c)*LL + i)*LL + jj] = lw;
        }
    }
}

// ================= 3. combine chunk matrices -> den; loss =================
__global__ void __launch_bounds__(512) combine_loss_kernel(const float* __restrict__ st,
                                                           const float* __restrict__ en,
                                                           float* __restrict__ out) {
    const float L2E = 1.4426950408889634f;
    __shared__ float nd[BB];
    int tid = threadIdx.x;
    int w = tid >> 5, lane = tid & 31;
    int jj = (lane < LL) ? lane : (LL-1);
    bool l9 = (lane < LL);

    for (int b = w; b < BB; b += 16) {
        float Mv[CH][LL];
        #pragma unroll
        for (int c = 0; c < CH; c++)
            #pragma unroll
            for (int i = 0; i < LL; i++)
                Mv[c][i] = g_lnM[(((b*CH) + c)*LL + i)*LL + jj];

        float v = l9 ? (st[lane] + g_logits[(size_t)b*SS*LL + lane]) * L2E : -1e30f;
        #pragma unroll
        for (int c = 0; c < CH; c++) {
            float s[LL];
            #pragma unroll
            for (int i = 0; i < LL; i++) s[i] = __shfl_sync(FULLM, v, i) + Mv[c][i];
            float mx = s[0];
            #pragma unroll
            for (int i = 1; i < LL; i++) mx = fmaxf(mx, s[i]);
            float p = 0.f;
            #pragma unroll
            for (int i = 0; i < LL; i++) p += ex2f(s[i] - mx);
            v = mx + lg2f(p);
        }
        float fv = l9 ? (v + en[lane] * L2E) : -1e30f;
        float s[LL];
        #pragma unroll
        for (int i = 0; i < LL; i++) s[i] = __shfl_sync(FULLM, fv, i);
        float mx = s[0];
        #pragma unroll
        for (int i = 1; i < LL; i++) mx = fmaxf(mx, s[i]);
        float p = 0.f;
        #pragma unroll
        for (int i = 0; i < LL; i++) p += ex2f(s[i] - mx);
        if (lane == 0) nd[b] = g_num[b] - (mx + lg2f(p)) * (1.0f / L2E);
    }
    __syncthreads();
    if (tid < 32) {
        float v = nd[tid] + nd[tid + 32];
        #pragma unroll
        for (int o = 16; o > 0; o >>= 1) v += __shfl_down_sync(FULLM, v, o);
        if (tid == 0) out[0] = -v / (float)BB;
    }
}

extern "C" void kernel_launch(void* const* d_in, const int* in_sizes, int n_in,
                              void* d_out, int out_size) {
    const float* hidden = (const float*)d_in[0];
    const int*   mask   = (const int*)  d_in[1];
    const int*   labels = (const int*)  d_in[2];
    const float* W      = (const float*)d_in[3];
    const float* bvec   = (const float*)d_in[4];
    const float* st     = (const float*)d_in[5];
    const float* en     = (const float*)d_in[6];
    const float* tr     = (const float*)d_in[7];
    float* out = (float*)d_out;

    gemm_kernel<<<BS/64, 256>>>(hidden, W, bvec);
    fused_kernel<<<BB*2, 384>>>(mask, labels, st, en, tr, out);
    combine_loss_kernel<<<1, 512>>>(st, en, out);
}

// round 8
// speedup vs baseline: 1.3005x; 1.0786x over previous
#include <cuda_runtime.h>

#define BB 64
#define SS 512
#define HH 768
#define LL 9
#define BS (BB*SS)
#define CH 4
#define CLEN 128
#define FULLM 0xffffffffu

__device__ float g_logits[BS*LL];
__device__ float g_num[BB];
__device__ float g_lnM[BB*CH*LL*LL];

__device__ __forceinline__ float ex2f(float x){ float y; asm("ex2.approx.ftz.f32 %0,%1;" : "=f"(y) : "f"(x)); return y; }
__device__ __forceinline__ float lg2f(float x){ float y; asm("lg2.approx.ftz.f32 %0,%1;" : "=f"(y) : "f"(x)); return y; }

// ================= 1. GEMM: 2 rows/lane, 8-way k-split, plain LDG, unroll 4 =================
__global__ void __launch_bounds__(256) gemm_kernel(const float* __restrict__ hidden,
                                                   const float* __restrict__ W,
                                                   const float* __restrict__ bvec) {
    __shared__ float w_t[LL*HH];   // [l][k]
    __shared__ float b_s[LL];
    int tid = threadIdx.x;
    for (int i = tid; i < HH*LL; i += 256) {
        int k = i / LL, l = i - k*LL;
        w_t[l*HH + k] = W[i];
    }
    if (tid < LL) b_s[tid] = bvec[tid];
    __syncthreads();

    int warp = tid >> 5, ln = tid & 31;
    int li = ln & 7;        // k-split lane
    int rg = ln >> 3;       // row group (2 rows)
    int row0 = blockIdx.x * 64 + warp * 8 + rg * 2;
    const float* hp = hidden + (size_t)row0 * HH;

    float acc0[LL], acc1[LL];
    #pragma unroll
    for (int l = 0; l < LL; l++) { acc0[l] = 0.f; acc1[l] = 0.f; }

    #pragma unroll 4
    for (int c = 0; c < HH/32; c++) {
        int kb = c*32 + li*4;
        float4 x0 = *reinterpret_cast<const float4*>(hp + kb);
        float4 x1 = *reinterpret_cast<const float4*>(hp + HH + kb);
        #pragma unroll
        for (int l = 0; l < LL; l++) {
            float4 w4 = *reinterpret_cast<const float4*>(w_t + l*HH + kb);
            acc0[l] += x0.x*w4.x; acc1[l] += x1.x*w4.x;
            acc0[l] += x0.y*w4.y; acc1[l] += x1.y*w4.y;
            acc0[l] += x0.z*w4.z; acc1[l] += x1.z*w4.z;
            acc0[l] += x0.w*w4.w; acc1[l] += x1.w*w4.w;
        }
    }
    #pragma unroll
    for (int l = 0; l < LL; l++) {
        float v0 = acc0[l], v1 = acc1[l];
        v0 += __shfl_xor_sync(FULLM, v0, 4); v1 += __shfl_xor_sync(FULLM, v1, 4);
        v0 += __shfl_xor_sync(FULLM, v0, 2); v1 += __shfl_xor_sync(FULLM, v1, 2);
        v0 += __shfl_xor_sync(FULLM, v0, 1); v1 += __shfl_xor_sync(FULLM, v1, 1);
        acc0[l] = v0; acc1[l] = v1;
    }
    if (li == 0) {
        float* op0 = g_logits + (size_t)row0 * LL;
        float* op1 = op0 + LL;
        #pragma unroll
        for (int l = 0; l < LL; l++) { op0[l] = acc0[l] + b_s[l]; op1[l] = acc1[l] + b_s[l]; }
    }
}

// ================= 2. fused: blocks 0..63 viterbi+num+onehot, 64..127 lognorm chunks =================
// Serial loops are BRANCH-FREE: arrays padded one step (t=512 is a masked no-op).
__global__ void __launch_bounds__(384) fused_kernel(const int* __restrict__ mask,
                                                    const int* __restrict__ labels,
                                                    const float* __restrict__ st,
                                                    const float* __restrict__ en,
                                                    const float* __restrict__ tr,
                                                    float* __restrict__ out) {
    const float L2E = 1.4426950408889634f;
    int bid = blockIdx.x;
    int tid = threadIdx.x;

    __shared__ float em_s[(SS+1)*LL];        // t=512 pad = 0
    __shared__ unsigned char m_sh[SS+1];     // m[512] = 0
    __shared__ unsigned char bp[SS+1][16];
    __shared__ unsigned char seg[8][LL][64];
    __shared__ unsigned char chosen[8];
    __shared__ int best_last_sh;

    int b = (bid < BB) ? bid : (bid - BB);
    // ---- stage emissions + mask + pads ----
    {
        const float4* src = reinterpret_cast<const float4*>(g_logits + (size_t)b * SS * LL);
        float4* dst = reinterpret_cast<float4*>(em_s);
        #pragma unroll
        for (int k = 0; k < 3; k++) dst[tid + k*384] = src[tid + k*384];
        const int* mp = mask + b * SS;
        for (int k = tid; k < SS; k += 384) m_sh[k] = (unsigned char)(mp[k] != 0);
        if (tid < LL) em_s[SS*LL + tid] = 0.f;
        if (tid == 0) m_sh[SS] = 0;
    }
    __syncthreads();

    int w = tid >> 5, j = tid & 31;

    if (bid < BB) {
        bool lane9 = (j < LL);
        if (w == 0) {
            // ---------------- exact Viterbi forward: 512 steps, branch-free ----------------
            float trow[LL];
            #pragma unroll
            for (int i = 0; i < LL; i++) trow[i] = lane9 ? tr[i*LL + j] : 0.f;
            float vs = lane9 ? (st[j] + em_s[j]) : -1e30f;
            for (int tt = 0; tt < 32; tt++) {
                #pragma unroll
                for (int k = 0; k < 16; k++) {
                    int t = tt*16 + k + 1;            // 1..512
                    float em_c = lane9 ? em_s[t*LL + j] : 0.f;
                    int m_c = m_sh[t];
                    float v[LL];
                    #pragma unroll
                    for (int i = 0; i < LL; i++) v[i] = __shfl_sync(FULLM, vs, i) + trow[i];
                    float m01 = fmaxf(v[0], v[1]), m23 = fmaxf(v[2], v[3]);
                    float m45 = fmaxf(v[4], v[5]), m67 = fmaxf(v[6], v[7]);
                    float best = fmaxf(fmaxf(fmaxf(m01, m23), fmaxf(m45, m67)), v[8]);
                    float nxt = best + em_c;
                    int bi = 8;
                    #pragma unroll
                    for (int i = 7; i >= 0; i--) bi = (v[i] == best) ? i : bi;
                    if (lane9) bp[t][j] = (unsigned char)(m_c ? bi : j);
                    vs = m_c ? nxt : vs;
                }
            }
            float fin = lane9 ? (vs + en[j]) : -1e30f;
            float bv = -1e30f; int bl = 0;
            #pragma unroll
            for (int i = 0; i < LL; i++) {
                float f = __shfl_sync(FULLM, fin, i);
                if (f > bv) { bv = f; bl = i; }
            }
            if (j == 0) best_last_sh = bl;
        } else if (w == 1) {
            // ---------------- numerator ----------------
            const int* lp = labels + b * SS;
            float acc = 0.f; int cnt = 0;
            for (int t = j; t < SS; t += 32) {
                int m = m_sh[t]; cnt += m;
                if (t >= 1 && m) {
                    int tg = lp[t];   if (tg == -100) tg = 0;
                    int tp = lp[t-1]; if (tp == -100) tp = 0;
                    acc += em_s[t*LL + tg] + tr[tp*LL + tg];
                }
            }
            #pragma unroll
            for (int o = 16; o > 0; o >>= 1) {
                acc += __shfl_down_sync(FULLM, acc, o);
                cnt += __shfl_down_sync(FULLM, cnt, o);
            }
            if (j == 0) {
                int t0 = lp[0]; if (t0 == -100) t0 = 0;
                int lt = lp[cnt - 1]; if (lt == -100) lt = 0;
                g_num[b] = st[t0] + em_s[t0] + acc + en[lt];
            }
        }
        __syncthreads();

        // ---------------- chunk-parallel backtrack: 72 chases ----------------
        if (tid < 72) {
            int c = tid / 9, e = tid - c*9;
            int thi = (c == 7) ? (SS-1) : (c*64 + 64);
            int cur = e;
            for (int t = thi; t >= c*64 + 1; t--) {
                cur = bp[t][cur];
                seg[c][e][t - 1 - c*64] = (unsigned char)cur;
            }
        }
        __syncthreads();
        if (tid == 0) {
            int cur = best_last_sh;
            chosen[7] = (unsigned char)cur;
            for (int c = 7; c >= 1; c--) {
                cur = seg[c][cur][0];
                chosen[c-1] = (unsigned char)cur;
            }
        }
        __syncthreads();

        // ---------------- one-hot write ----------------
        float* outp = out + 1 + (size_t)b * SS * LL;
        int bl = best_last_sh;
        for (int idx = tid; idx < SS*LL; idx += 384) {
            int t = idx / LL;
            int l = idx - t*LL;
            int c = t >> 6;
            int tag = (t == SS-1) ? bl : (int)seg[c][chosen[c]][t & 63];
            outp[idx] = (m_sh[t] && tag == l) ? 1.f : 0.f;
        }
    } else {
        // ---------------- lognorm chunk transfer matrices (branch-free, 8x16) ----------------
        int c = w / 3, trio = w - c*3;
        int lane = j;
        int gg = lane / 9;
        int jj = lane - gg*9;
        if (gg > 2) { gg = 0; jj = lane - 27; }
        int gbase = gg * 9;
        bool act = (lane < 27);
        int i = trio*3 + (lane < 27 ? lane/9 : 0);

        float u[LL];
        #pragma unroll
        for (int k = 0; k < LL; k++) u[k] = ex2f(tr[k*LL + jj] * L2E);

        float wv = (act && jj == i) ? 1.f : 0.f;
        int Ce = 0;
        int t0 = c*CLEN + 1;
        for (int oo = 0; oo < 8; oo++) {
            #pragma unroll
            for (int k = 0; k < 16; k++) {
                int t = t0 + oo*16 + k;              // t=512 masked no-op
                float pe = ex2f(em_s[t*LL + jj] * L2E);
                int m = m_sh[t];
                float wi[LL];
                #pragma unroll
                for (int q = 0; q < LL; q++) wi[q] = __shfl_sync(FULLM, wv, gbase + q) * u[q];
                float p = ((wi[0]+wi[1]) + (wi[2]+wi[3])) + ((wi[4]+wi[5]) + (wi[6]+wi[7])) + wi[8];
                float nw = p * pe;
                wv = m ? nw : wv;
            }
            float mx = wv;
            #pragma unroll
            for (int q = 0; q < LL; q++) mx = fmaxf(mx, __shfl_sync(FULLM, wv, gbase + q));
            int e = ((__float_as_int(mx) >> 23) & 0xFF) - 127;
            Ce += e;
            wv *= __int_as_float((127 - e) << 23);
        }
        if (act) {
            float lw = lg2f(wv) + (float)Ce;
            g_lnM[(((b*CH) + c)*LL + i)*LL + jj] = lw;
        }
    }
}

// ================= 3. combine chunk matrices -> den; loss =================
__global__ void __launch_bounds__(512) combine_loss_kernel(const float* __restrict__ st,
                                                           const float* __restrict__ en,
                                                           float* __restrict__ out) {
    const float L2E = 1.4426950408889634f;
    __shared__ float nd[BB];
    int tid = threadIdx.x;
    int w = tid >> 5, lane = tid & 31;
    int jj = (lane < LL) ? lane : (LL-1);
    bool l9 = (lane < LL);

    for (int b = w; b < BB; b += 16) {
        float Mv[CH][LL];
        #pragma unroll
        for (int c = 0; c < CH; c++)
            #pragma unroll
            for (int i = 0; i < LL; i++)
                Mv[c][i] = g_lnM[(((b*CH) + c)*LL + i)*LL + jj];

        float v = l9 ? (st[lane] + g_logits[(size_t)b*SS*LL + lane]) * L2E : -1e30f;
        #pragma unroll
        for (int c = 0; c < CH; c++) {
            float s[LL];
            #pragma unroll
            for (int i = 0; i < LL; i++) s[i] = __shfl_sync(FULLM, v, i) + Mv[c][i];
            float mx = s[0];
            #pragma unroll
            for (int i = 1; i < LL; i++) mx = fmaxf(mx, s[i]);
            float p = 0.f;
            #pragma unroll
            for (int i = 0; i < LL; i++) p += ex2f(s[i] - mx);
            v = mx + lg2f(p);
        }
        float fv = l9 ? (v + en[lane] * L2E) : -1e30f;
        float s[LL];
        #pragma unroll
        for (int i = 0; i < LL; i++) s[i] = __shfl_sync(FULLM, fv, i);
        float mx = s[0];
        #pragma unroll
        for (int i = 1; i < LL; i++) mx = fmaxf(mx, s[i]);
        float p = 0.f;
        #pragma unroll
        for (int i = 0; i < LL; i++) p += ex2f(s[i] - mx);
        if (lane == 0) nd[b] = g_num[b] - (mx + lg2f(p)) * (1.0f / L2E);
    }
    __syncthreads();
    if (tid < 32) {
        float v = nd[tid] + nd[tid + 32];
        #pragma unroll
        for (int o = 16; o > 0; o >>= 1) v += __shfl_down_sync(FULLM, v, o);
        if (tid == 0) out[0] = -v / (float)BB;
    }
}

extern "C" void kernel_launch(void* const* d_in, const int* in_sizes, int n_in,
                              void* d_out, int out_size) {
    const float* hidden = (const float*)d_in[0];
    const int*   mask   = (const int*)  d_in[1];
    const int*   labels = (const int*)  d_in[2];
    const float* W      = (const float*)d_in[3];
    const float* bvec   = (const float*)d_in[4];
    const float* st     = (const float*)d_in[5];
    const float* en     = (const float*)d_in[6];
    const float* tr     = (const float*)d_in[7];
    float* out = (float*)d_out;

    gemm_kernel<<<BS/64, 256>>>(hidden, W, bvec);
    fused_kernel<<<BB*2, 384>>>(mask, labels, st, en, tr, out);
    combine_loss_kernel<<<1, 512>>>(st, en, out);
}